// round 8
// baseline (speedup 1.0000x reference)
#include <cuda_runtime.h>
#include <cstdint>

typedef unsigned long long ull;

#define B_   32
#define T_   2048
#define IN0  128
#define H_   512
#define OD_  128
#define NBLK 128
#define NTHR 256

#define OUT_OFF_HIDDEN 8388608   // 32*2048*128
#define OUT_OFF_CN     8396800   // + 2*32*128

// ---------------- device scratch (static; no allocation) ----------------
__device__ float g_xT[(size_t)T_ * B_ * IN0];     // x transposed  [t][b][d]
__device__ float g_out0T[(size_t)T_ * B_ * H_];   // layer0 h      [t][b][h]
__device__ float g_out1T[(size_t)T_ * B_ * H_];   // layer1 h      [t][b][h]
__device__ float g_fcwT[H_ * OD_];                // fc_w^T        [k][o]
__device__ float g_hbuf[2 * B_ * H_];             // double-buffered h [buf][b][h]
__device__ unsigned g_bar_count;                  // zero-init
__device__ volatile unsigned g_bar_gen;           // zero-init

// ---------------- helpers ----------------
__device__ __forceinline__ ull pack2(float a, float b) {
    ull r; asm("mov.b64 %0, {%1, %2};" : "=l"(r) : "f"(a), "f"(b)); return r;
}
__device__ __forceinline__ void ffma2(ull &d, ull a, ull b) {
    asm("fma.rn.f32x2 %0, %1, %2, %0;" : "+l"(d) : "l"(a), "l"(b));
}
__device__ __forceinline__ float fold2(ull v) {
    return __uint_as_float((unsigned)v) + __uint_as_float((unsigned)(v >> 32));
}
__device__ __forceinline__ float sigf(float x) { return 1.f / (1.f + __expf(-x)); }

__device__ __forceinline__ void grid_barrier() {
    __syncthreads();
    if (threadIdx.x == 0) {
        __threadfence();
        unsigned my = g_bar_gen;
        if (atomicAdd(&g_bar_count, 1u) == gridDim.x - 1) {
            g_bar_count = 0;
            __threadfence();
            g_bar_gen = my + 1;
        } else {
            while (g_bar_gen == my) { __nanosleep(64); }
        }
        __threadfence();
    }
    __syncthreads();
}

// ---------------- transpose x: [b][t][d] -> [t][b][d] ----------------
__global__ void transpose_x_kernel(const float* __restrict__ x) {
    int idx = blockIdx.x * NTHR + threadIdx.x;     // float4 index, 2,097,152 total
    int c = idx & 31;                              // 32 float4 per 128-float row
    int r = idx >> 5;                              // r = b*2048 + t
    int b = r >> 11;
    int t = r & 2047;
    float4 v = *(const float4*)(x + (size_t)idx * 4);
    *(float4*)(g_xT + ((size_t)t * B_ + b) * IN0 + c * 4) = v;
}

// ---------------- transpose fc_w: [o][k] -> [k][o] ----------------
__global__ void transpose_fcw_kernel(const float* __restrict__ fw) {
    int idx = blockIdx.x * NTHR + threadIdx.x;     // 65536 total
    int o = idx >> 9;
    int k = idx & 511;
    g_fcwT[k * OD_ + o] = fw[idx];
}

// ---------------- persistent LSTM layer ----------------
// 128 blocks; block owns hidden units u0..u0+3 -> 16 gate rows (r = gate*4 + j).
// Per step: v=[x_t; h_{t-1}] -> SMEM (swizzled); 4x4-tiled f32x2 GEMV (k-split 8
// warps); SMEM reduce; activations (c in registers of threads 0..127);
// h -> global double buffer + out buffer; grid barrier.
template<int IN, int K, int LAYER>
__global__ __launch_bounds__(NTHR, 1)
void lstm_kernel(const float* __restrict__ w_ih,
                 const float* __restrict__ w_hh,
                 const float* __restrict__ b_ih,
                 const float* __restrict__ b_hh,
                 float* __restrict__ dout)
{
    const float* xT  = LAYER ? g_out0T : g_xT;
    float*       oT  = LAYER ? g_out1T : g_out0T;

    extern __shared__ float sm[];
    float* W_s    = sm;                         // 16*K
    float* v_s    = W_s + 16 * K;               // 32*K
    float* red_s  = v_s + 32 * K;               // 8*580
    float* bias_s = red_s + 8 * 580;            // 16
    float* hst    = bias_s + 16;                // 128

    const int tid = threadIdx.x;
    const int bid = blockIdx.x;
    const int u0  = bid * 4;
    const int C   = K / 4;                      // float4 chunks per row

    // ---- load W slice (swizzled low-2 chunk bits keyed by reader rgrp=r>>2) ----
    for (int q = tid; q < 16 * C; q += NTHR) {
        int r = q / C, c = q % C;
        int row = (r >> 2) * H_ + u0 + (r & 3); // gate*H + unit
        int k = c * 4;
        float4 w;
        if (k < IN) w = *(const float4*)(w_ih + (size_t)row * IN + k);
        else        w = *(const float4*)(w_hh + (size_t)row * H_ + (k - IN));
        int slot = (c & ~3) | ((c ^ (r >> 2)) & 3);
        *(float4*)(W_s + r * K + slot * 4) = w;
    }
    if (tid < 16) {
        int row = (tid >> 2) * H_ + u0 + (tid & 3);
        bias_s[tid] = b_ih[row] + b_hh[row];
    }
    // zero h double-buffer slot read at t=0 (buffer 1)
    if (tid < 128) g_hbuf[B_ * H_ + bid * 128 + tid] = 0.f;

    const int ks   = tid >> 5;                  // k-slice (warp), 0..7
    const int lane = tid & 31;
    const int rg   = lane >> 3;                 // row group 0..3  (rows rg*4+i)
    const int bg   = lane & 7;                  // batch group 0..7 (b = bg*4+j)

    // swizzle folds to constant offsets (k stride = 8 chunks preserves low bits)
    const int wbase = ((ks & ~3) + ((ks ^ rg) & 3)) * 4;   // + r*K + it*32
    const int vbase = ((ks ^ bg) & 7) * 4;                 // + b*K + it*32

    float creg = 0.f;                           // c for (jj=tid>>5, b=tid&31) on tid<128

    grid_barrier();                             // hbuf zero + W visible

    const int ITER = K / 32;
    for (int t = 0; t < T_; ++t) {
        const int pb = (t & 1) ^ 1;
        const int cb = t & 1;

        // ---- load v = [x_t ; h_{t-1}] (swizzled; h via L2 to dodge stale L1) ----
        const float* xrow = xT + (size_t)t * (B_ * IN);
        const float* hrow = g_hbuf + pb * (B_ * H_);
        for (int q = tid; q < 32 * C; q += NTHR) {
            int b = q / C, c = q % C;
            int k = c * 4;
            float4 v;
            if (k < IN) v = *(const float4*)(xrow + b * IN + k);
            else        v = __ldcg((const float4*)(hrow + b * H_ + (k - IN)));
            int slot = (c & ~7) | ((c ^ (b >> 2)) & 7);
            *(float4*)(v_s + b * K + slot * 4) = v;
        }
        __syncthreads();

        // ---- 4x4 register-tiled GEMV, f32x2 ----
        ull acc[4][4];
        #pragma unroll
        for (int i = 0; i < 4; i++)
            #pragma unroll
            for (int j = 0; j < 4; j++) acc[i][j] = 0ull;

        #pragma unroll 2
        for (int it = 0; it < ITER; ++it) {
            const int off = it * 32;
            float4 wf[4], vf[4];
            #pragma unroll
            for (int i = 0; i < 4; i++)
                wf[i] = *(const float4*)(W_s + (rg * 4 + i) * K + wbase + off);
            #pragma unroll
            for (int j = 0; j < 4; j++)
                vf[j] = *(const float4*)(v_s + (bg * 4 + j) * K + vbase + off);
            ull vlo[4], vhi[4];
            #pragma unroll
            for (int j = 0; j < 4; j++) {
                vlo[j] = pack2(vf[j].x, vf[j].y);
                vhi[j] = pack2(vf[j].z, vf[j].w);
            }
            #pragma unroll
            for (int i = 0; i < 4; i++) {
                ull wlo = pack2(wf[i].x, wf[i].y);
                ull whi = pack2(wf[i].z, wf[i].w);
                #pragma unroll
                for (int j = 0; j < 4; j++) {
                    ffma2(acc[i][j], wlo, vlo[j]);
                    ffma2(acc[i][j], whi, vhi[j]);
                }
            }
        }

        // ---- fold + per-k-slice partials to SMEM ----
        #pragma unroll
        for (int i = 0; i < 4; i++) {
            int r = rg * 4 + i;
            float4 s;
            s.x = fold2(acc[i][0]); s.y = fold2(acc[i][1]);
            s.z = fold2(acc[i][2]); s.w = fold2(acc[i][3]);
            *(float4*)(red_s + ks * 580 + r * 36 + bg * 4) = s;
        }
        __syncthreads();

        // ---- reduce 8 slices, activations, c/h update ----
        if (tid < 128) {
            int jj = tid >> 5;                  // unit 0..3
            int b  = tid & 31;
            float gs[4];
            #pragma unroll
            for (int g = 0; g < 4; g++) {
                int r = g * 4 + jj;
                float s = bias_s[r];
                #pragma unroll
                for (int k2 = 0; k2 < 8; k2++) s += red_s[k2 * 580 + r * 36 + b];
                gs[g] = s;
            }
            float ig = sigf(gs[0]);
            float fg = sigf(gs[1]);
            float gg = tanhf(gs[2]);
            float og = sigf(gs[3]);
            creg = fg * creg + ig * gg;
            hst[jj * 32 + b] = og * tanhf(creg);
            if (t == T_ - 1)
                dout[OUT_OFF_CN + LAYER * (B_ * H_) + b * H_ + u0 + jj] = creg;
        }
        __syncthreads();

        // ---- publish h (double buffer + out sequence) ----
        if (tid < 32) {
            float4 h4;
            h4.x = hst[tid]; h4.y = hst[32 + tid];
            h4.z = hst[64 + tid]; h4.w = hst[96 + tid];
            size_t didx = (size_t)tid * H_ + u0;
            *(float4*)(g_hbuf + cb * (B_ * H_) + didx) = h4;
            *(float4*)(oT + (size_t)t * (B_ * H_) + didx) = h4;
            __threadfence();
        }
        grid_barrier();
    }
}

// ---------------- FC: out = relu(h) @ fc_w^T + fc_b ----------------
// 8 (b,t) pairs per block, 128 threads; thread owns 4 outputs (o = lane*4..+3),
// k split over 4 warps, f32x2 pairs along o. Blocks >= 8192 handle `hidden`.
#define FCP 8
__global__ __launch_bounds__(128, 8)
void fc_kernel(const float* __restrict__ fc_b, float* __restrict__ dout)
{
    __shared__ float hs[FCP * H_];              // 16 KB, relu'd activations
    __shared__ float red[4 * 32 * 33];          // [w*32+lane][33] partials

    const int tid  = threadIdx.x;
    const int blk  = blockIdx.x;
    const int w    = tid >> 5;
    const int lane = tid & 31;
    const bool hidden = (blk >= 8192);

    // ---- load + relu activations ----
    for (int q = tid; q < FCP * (H_ / 4); q += 128) {
        int p = q >> 7, c = q & 127;
        float4 v;
        if (!hidden) {
            int pair = blk * FCP + p;
            int b = pair >> 11, t = pair & 2047;
            v = *(const float4*)(g_out1T + ((size_t)t * B_ + b) * H_ + c * 4);
        } else {
            int p2 = (blk - 8192) * FCP + p;
            int l = p2 >> 5, b = p2 & 31;
            const float* sp = l ? g_out1T : g_out0T;
            v = *(const float4*)(sp + ((size_t)(T_ - 1) * B_ + b) * H_ + c * 4);
        }
        v.x = fmaxf(v.x, 0.f); v.y = fmaxf(v.y, 0.f);
        v.z = fmaxf(v.z, 0.f); v.w = fmaxf(v.w, 0.f);
        *(float4*)(hs + p * H_ + c * 4) = v;
    }
    __syncthreads();

    const int o4 = lane * 4;
    ull acc[FCP][2];
    #pragma unroll
    for (int p = 0; p < FCP; p++) { acc[p][0] = 0ull; acc[p][1] = 0ull; }

    #pragma unroll 4
    for (int i = 0; i < H_ / 4; ++i) {
        int k = w + i * 4;
        float4 wv = *(const float4*)(g_fcwT + k * OD_ + o4);
        ull wlo = pack2(wv.x, wv.y);
        ull whi = pack2(wv.z, wv.w);
        #pragma unroll
        for (int p = 0; p < FCP; p++) {
            float h = hs[p * H_ + k];
            ull hd = pack2(h, h);
            ffma2(acc[p][0], wlo, hd);
            ffma2(acc[p][1], whi, hd);
        }
    }

    // ---- stash partials (components are distinct o's; no fold) ----
    {
        float* row = red + (w * 32 + lane) * 33;
        #pragma unroll
        for (int p = 0; p < FCP; p++) {
            row[p * 4 + 0] = __uint_as_float((unsigned)acc[p][0]);
            row[p * 4 + 1] = __uint_as_float((unsigned)(acc[p][0] >> 32));
            row[p * 4 + 2] = __uint_as_float((unsigned)acc[p][1]);
            row[p * 4 + 3] = __uint_as_float((unsigned)(acc[p][1] >> 32));
        }
    }
    __syncthreads();

    // ---- cross-warp reduce + bias + store ----
    int p  = tid >> 4;
    int og = (tid & 15) * 8;
    size_t dst;
    if (!hidden) dst = (size_t)(blk * FCP + p) * OD_;
    else         dst = (size_t)OUT_OFF_HIDDEN + ((blk - 8192) * FCP + p) * OD_;
    #pragma unroll
    for (int oo = 0; oo < 8; oo++) {
        int o = og + oo;
        float s = fc_b[o];
        #pragma unroll
        for (int ww = 0; ww < 4; ww++)
            s += red[(ww * 32 + (o >> 2)) * 33 + p * 4 + (o & 3)];
        dout[dst + o] = s;
    }
}

// ---------------- host ----------------
#define SMEM0 ((16*640 + 32*640 + 8*580 + 16 + 128) * 4)    // 142016 B
#define SMEM1 ((16*1024 + 32*1024 + 8*580 + 16 + 128) * 4)  // 215744 B

extern "C" void kernel_launch(void* const* d_in, const int* in_sizes, int n_in,
                              void* d_out, int out_size) {
    (void)in_sizes; (void)n_in; (void)out_size;
    const float* x     = (const float*)d_in[0];
    const float* w_ih0 = (const float*)d_in[1];
    const float* w_hh0 = (const float*)d_in[2];
    const float* b_ih0 = (const float*)d_in[3];
    const float* b_hh0 = (const float*)d_in[4];
    const float* w_ih1 = (const float*)d_in[5];
    const float* w_hh1 = (const float*)d_in[6];
    const float* b_ih1 = (const float*)d_in[7];
    const float* b_hh1 = (const float*)d_in[8];
    const float* fc_w  = (const float*)d_in[9];
    const float* fc_b  = (const float*)d_in[10];
    float* out = (float*)d_out;

    cudaFuncSetAttribute(lstm_kernel<IN0, IN0 + H_, 0>,
                         cudaFuncAttributeMaxDynamicSharedMemorySize, SMEM0);
    cudaFuncSetAttribute(lstm_kernel<H_, H_ + H_, 1>,
                         cudaFuncAttributeMaxDynamicSharedMemorySize, SMEM1);

    transpose_x_kernel<<<8192, NTHR>>>(x);
    transpose_fcw_kernel<<<256, NTHR>>>(fc_w);
    lstm_kernel<IN0, IN0 + H_, 0><<<NBLK, NTHR, SMEM0>>>(w_ih0, w_hh0, b_ih0, b_hh0, out);
    lstm_kernel<H_, H_ + H_, 1><<<NBLK, NTHR, SMEM1>>>(w_ih1, w_hh1, b_ih1, b_hh1, out);
    fc_kernel<<<8192 + 8, 128>>>(fc_b, out);
}

// round 12
// speedup vs baseline: 1.5445x; 1.5445x over previous
#include <cuda_runtime.h>
#include <cstdint>

typedef unsigned long long ull;

#define B_   32
#define T_   2048
#define IN0  128
#define H_   512
#define OD_  128
#define NBLK 128
#define NTHR 256

#define OUT_OFF_HIDDEN 8388608   // 32*2048*128
#define OUT_OFF_CN     8396800   // + 2*32*128

// ---------------- device scratch (static; no allocation) ----------------
__device__ float g_xT[(size_t)T_ * B_ * IN0];     // x transposed  [t][b][d]
__device__ float g_out0T[(size_t)T_ * B_ * H_];   // layer0 h      [t][b][h]
__device__ float g_out1T[(size_t)T_ * B_ * H_];   // layer1 h      [t][b][h]
__device__ float g_gx[(size_t)T_ * B_ * 4 * H_];  // gate x-projections [t][b][4H]
__device__ float g_wT[H_ * 4 * H_];               // w_ih^T (K-major) [k][4H]
__device__ float g_fcwT[H_ * OD_];                // fc_w^T  [k][o]
__device__ float g_hbuf[2 * B_ * H_];             // double-buffered h [buf][b][h]
__device__ unsigned g_cnt[2];                     // barrier counters (reset each launch)

// ---------------- helpers ----------------
__device__ __forceinline__ ull pack2(float a, float b) {
    ull r; asm("mov.b64 %0, {%1, %2};" : "=l"(r) : "f"(a), "f"(b)); return r;
}
__device__ __forceinline__ void ffma2(ull &d, ull a, ull b) {
    asm("fma.rn.f32x2 %0, %1, %2, %0;" : "+l"(d) : "l"(a), "l"(b));
}
__device__ __forceinline__ float fold2(ull v) {
    return __uint_as_float((unsigned)v) + __uint_as_float((unsigned)(v >> 32));
}
__device__ __forceinline__ void unpack2(ull v, float &a, float &b) {
    a = __uint_as_float((unsigned)v); b = __uint_as_float((unsigned)(v >> 32));
}
__device__ __forceinline__ float sigf(float x) { return 1.f / (1.f + __expf(-x)); }

__device__ __forceinline__ void cp16(float* dst_smem, const float* src) {
    unsigned d = (unsigned)__cvta_generic_to_shared(dst_smem);
    asm volatile("cp.async.cg.shared.global [%0], [%1], 16;" :: "r"(d), "l"(src));
}
#define CP_COMMIT() asm volatile("cp.async.commit_group;")
#define CP_WAIT(n)  asm volatile("cp.async.wait_group %0;" :: "n"(n))

__device__ __forceinline__ unsigned ld_acq(const unsigned* p) {
    unsigned v;
    asm volatile("ld.acquire.gpu.global.u32 %0, [%1];" : "=r"(v) : "l"(p));
    return v;
}
__device__ __forceinline__ void red_add(unsigned* p, unsigned v) {
    asm volatile("red.relaxed.gpu.global.add.u32 [%0], %1;" :: "l"(p), "r"(v) : "memory");
}

// ---------------- transpose x: [b][t][d] -> [t][b][d] (+ counter reset) ----------------
__global__ void transpose_x_kernel(const float* __restrict__ x) {
    if (blockIdx.x == 0 && threadIdx.x == 0) { g_cnt[0] = 0; g_cnt[1] = 0; }
    int idx = blockIdx.x * NTHR + threadIdx.x;     // float4 index, 2,097,152 total
    int c = idx & 31;
    int r = idx >> 5;                              // r = b*2048 + t
    int b = r >> 11;
    int t = r & 2047;
    float4 v = *(const float4*)(x + (size_t)idx * 4);
    *(float4*)(g_xT + ((size_t)t * B_ + b) * IN0 + c * 4) = v;
}

// ---------------- transpose w_ih: [4H][K] -> [K][4H] ----------------
template<int K>
__global__ void transpose_w_kernel(const float* __restrict__ w) {
    int idx = blockIdx.x * NTHR + threadIdx.x;     // 2048*K total
    int n = idx / K, k = idx % K;
    g_wT[k * (4 * H_) + n] = w[idx];
}

// ---------------- transpose fc_w: [o][k] -> [k][o] ----------------
__global__ void transpose_fcw_kernel(const float* __restrict__ fw) {
    int idx = blockIdx.x * NTHR + threadIdx.x;     // 65536 total
    int o = idx >> 9;
    int k = idx & 511;
    g_fcwT[k * OD_ + o] = fw[idx];
}

// ---------------- GEMM: gx = A @ w_ih^T + (b_ih + b_hh) ----------------
// A [M=65536, K] row-major (t*32+b major), B = g_wT [K, 2048], C = g_gx [M, 2048].
// 128x128 tile, 256 threads, 8x8 micro (split 4+4 with stride 64), cp.async dbl buf.
template<int K, int SRC>
__global__ __launch_bounds__(256, 2) void gemm_gx_kernel(
    const float* __restrict__ bih, const float* __restrict__ bhh)
{
    const float* A = SRC ? g_out0T : g_xT;
    __shared__ float As[2][128][20];   // [buf][m][k] (pad 20)
    __shared__ float Bs[2][16][128];   // [buf][k][n]
    __shared__ float bias_s[128];

    const int tid = threadIdx.x;
    const int tx = tid & 15, ty = tid >> 4;
    const int Mb = blockIdx.x * 128;
    const int Nb = blockIdx.y * 128;
    const int KT = K / 16;

    if (tid < 128) bias_s[tid] = bih[Nb + tid] + bhh[Nb + tid];

    // tile loader
    auto load_tiles = [&](int kt, int buf) {
        #pragma unroll
        for (int s = 0; s < 2; s++) {
            int q = tid + 256 * s;                  // A: 512 float4
            int r = q >> 2, c4 = q & 3;
            cp16(&As[buf][r][c4 * 4], A + (size_t)(Mb + r) * K + kt * 16 + c4 * 4);
        }
        #pragma unroll
        for (int s = 0; s < 2; s++) {
            int q = tid + 256 * s;                  // B: 512 float4
            int kk = q >> 5, n4 = q & 31;
            cp16(&Bs[buf][kk][n4 * 4], g_wT + (size_t)(kt * 16 + kk) * (4 * H_) + Nb + n4 * 4);
        }
    };

    ull acc[8][4];
    #pragma unroll
    for (int m = 0; m < 8; m++)
        #pragma unroll
        for (int p = 0; p < 4; p++) acc[m][p] = 0ull;

    int buf = 0;
    load_tiles(0, 0); CP_COMMIT();
    for (int kt = 0; kt < KT; ++kt) {
        if (kt + 1 < KT) { load_tiles(kt + 1, buf ^ 1); CP_COMMIT(); CP_WAIT(1); }
        else             { CP_WAIT(0); }
        __syncthreads();
        #pragma unroll
        for (int kk4 = 0; kk4 < 4; kk4++) {
            float4 a4[8];
            #pragma unroll
            for (int i = 0; i < 4; i++) {
                a4[i]     = *(const float4*)&As[buf][ty * 4 + i][kk4 * 4];
                a4[4 + i] = *(const float4*)&As[buf][64 + ty * 4 + i][kk4 * 4];
            }
            #pragma unroll
            for (int i2 = 0; i2 < 4; i2++) {
                int kk = kk4 * 4 + i2;
                float4 bA = *(const float4*)&Bs[buf][kk][tx * 4];
                float4 bB = *(const float4*)&Bs[buf][kk][64 + tx * 4];
                ull bp[4];
                bp[0] = pack2(bA.x, bA.y); bp[1] = pack2(bA.z, bA.w);
                bp[2] = pack2(bB.x, bB.y); bp[3] = pack2(bB.z, bB.w);
                #pragma unroll
                for (int m = 0; m < 8; m++) {
                    float av = (i2 == 0) ? a4[m].x : (i2 == 1) ? a4[m].y : (i2 == 2) ? a4[m].z : a4[m].w;
                    ull ad = pack2(av, av);
                    #pragma unroll
                    for (int p = 0; p < 4; p++) ffma2(acc[m][p], ad, bp[p]);
                }
            }
        }
        __syncthreads();
        buf ^= 1;
    }

    // epilogue: unpack (pairs are adjacent n!), add bias, store
    #pragma unroll
    for (int m = 0; m < 8; m++) {
        int mrow = (m < 4) ? (ty * 4 + m) : (64 + ty * 4 + (m - 4));
        size_t row = (size_t)(Mb + mrow) * (4 * H_);
        float4 q0, q1;
        unpack2(acc[m][0], q0.x, q0.y); unpack2(acc[m][1], q0.z, q0.w);
        unpack2(acc[m][2], q1.x, q1.y); unpack2(acc[m][3], q1.z, q1.w);
        q0.x += bias_s[tx * 4 + 0]; q0.y += bias_s[tx * 4 + 1];
        q0.z += bias_s[tx * 4 + 2]; q0.w += bias_s[tx * 4 + 3];
        q1.x += bias_s[64 + tx * 4 + 0]; q1.y += bias_s[64 + tx * 4 + 1];
        q1.z += bias_s[64 + tx * 4 + 2]; q1.w += bias_s[64 + tx * 4 + 3];
        *(float4*)(g_gx + row + Nb + tx * 4) = q0;
        *(float4*)(g_gx + row + Nb + 64 + tx * 4) = q1;
    }
}

// ---------------- persistent recurrent LSTM (K=512, h only) ----------------
// 128 blocks own 4 units (16 gate rows). Per step: cp.async h (2 halves) + gx;
// 4x8-tiled f32x2 GEMV, 16 k-slices; SMEM reduce; activations; publish; barrier.
template<int L>
__global__ __launch_bounds__(NTHR, 1)
void lstm_rec_kernel(const float* __restrict__ whh, float* __restrict__ dout)
{
    float* oT = L ? g_out1T : g_out0T;
    unsigned* cnt = &g_cnt[L];

    extern __shared__ float sm[];
    float* W_s  = sm;                    // 16*512 = 8192
    float* v_s  = W_s + 8192;            // 32*512 = 16384
    float* red_s = v_s + 16384;          // 16*580 = 9280
    float* gx_s = red_s + 9280;          // 512
    float* hst  = gx_s + 512;            // 128

    const int tid = threadIdx.x;
    const int bid = blockIdx.x;
    const int u0  = bid * 4;

    // ---- W fill (3-bit swizzle keyed by reader's rg = r>>2) ----
    for (int q = tid; q < 16 * 128; q += NTHR) {
        int r = q >> 7, c = q & 127;
        int grow = (r >> 2) * H_ + u0 + (r & 3);
        float4 w = *(const float4*)(whh + (size_t)grow * H_ + c * 4);
        int slot = (c & ~7) | ((c ^ ((r >> 2) << 1)) & 7);
        *(float4*)(W_s + r * 512 + slot * 4) = w;
    }
    // zero h double-buffer slot read at t=0 (buffer 1)
    if (tid < 128) g_hbuf[B_ * H_ + bid * 128 + tid] = 0.f;

    const int ks = tid >> 4;             // k-slice 0..15  (chunks ks+16i)
    const int rg = (tid >> 2) & 3;       // row group (rows rg*4+i)
    const int bg = tid & 3;              // batch group (b = bg*8+j)
    const int wbase = ((ks & ~7) | ((ks ^ (rg << 1)) & 7)) * 4;
    const int vbase = ((ks & ~7) | ((ks ^ (bg << 1)) & 7)) * 4;

    // v cp.async assignment: b = tid>>3, c = (tid&7) + 8p
    const int vb = tid >> 3, c0 = tid & 7;
    const int vsl = (c0 ^ ((vb >> 3) << 1)) & 7;
    float* vdst = v_s + vb * 512 + vsl * 4;

    float creg = 0.f;                    // c for (unit=tid>>5, b=tid&31) on tid<128

    // ---- init barrier ----
    __syncthreads();
    if (tid == 0) { __threadfence(); red_add(cnt, 1u); }
    if ((tid & 31) == 0) { while (ld_acq(cnt) < 128u) __nanosleep(32); }
    __syncthreads();

    for (int t = 0; t < T_; ++t) {
        const int pb = (t & 1) ^ 1;
        const int cb = t & 1;
        const float* hrow = g_hbuf + pb * (B_ * H_);
        const float* vsrc = hrow + vb * 512 + c0 * 4;

        // ---- group A: first-half h (k<256) + gx[t] slice ----
        #pragma unroll
        for (int p = 0; p < 8; p++) cp16(vdst + 32 * p, vsrc + 32 * p);
        if (tid < 128) {
            int b = tid >> 2, g = tid & 3;
            cp16(gx_s + tid * 4, g_gx + ((size_t)t * B_ + b) * (4 * H_) + g * H_ + u0);
        }
        CP_COMMIT();
        // ---- group B: second-half h ----
        #pragma unroll
        for (int p = 8; p < 16; p++) cp16(vdst + 32 * p, vsrc + 32 * p);
        CP_COMMIT();

        ull acc[4][8];
        #pragma unroll
        for (int i = 0; i < 4; i++)
            #pragma unroll
            for (int j = 0; j < 8; j++) acc[i][j] = 0ull;

        CP_WAIT(1); __syncthreads();

        #pragma unroll
        for (int half = 0; half < 2; half++) {
            if (half == 1) { CP_WAIT(0); __syncthreads(); }
            #pragma unroll
            for (int i = half * 4; i < half * 4 + 4; i++) {
                const int off = i * 64;
                float4 wf[4], vf[8];
                #pragma unroll
                for (int r = 0; r < 4; r++)
                    wf[r] = *(const float4*)(W_s + (rg * 4 + r) * 512 + wbase + off);
                #pragma unroll
                for (int j = 0; j < 8; j++)
                    vf[j] = *(const float4*)(v_s + (bg * 8 + j) * 512 + vbase + off);
                ull vl[8], vh[8];
                #pragma unroll
                for (int j = 0; j < 8; j++) {
                    vl[j] = pack2(vf[j].x, vf[j].y);
                    vh[j] = pack2(vf[j].z, vf[j].w);
                }
                #pragma unroll
                for (int r = 0; r < 4; r++) {
                    ull wl = pack2(wf[r].x, wf[r].y);
                    ull wh = pack2(wf[r].z, wf[r].w);
                    #pragma unroll
                    for (int j = 0; j < 8; j++) {
                        ffma2(acc[r][j], wl, vl[j]);
                        ffma2(acc[r][j], wh, vh[j]);
                    }
                }
            }
        }

        // ---- partials to SMEM ----
        #pragma unroll
        for (int r = 0; r < 4; r++) {
            float4 s0, s1;
            s0.x = fold2(acc[r][0]); s0.y = fold2(acc[r][1]);
            s0.z = fold2(acc[r][2]); s0.w = fold2(acc[r][3]);
            s1.x = fold2(acc[r][4]); s1.y = fold2(acc[r][5]);
            s1.z = fold2(acc[r][6]); s1.w = fold2(acc[r][7]);
            float* rp = red_s + ks * 580 + (rg * 4 + r) * 36 + bg * 8;
            *(float4*)(rp) = s0;
            *(float4*)(rp + 4) = s1;
        }
        __syncthreads();

        // ---- reduce + activations + c/h ----
        if (tid < 128) {
            int jj = tid >> 5;           // unit
            int b  = tid & 31;
            float gs[4];
            #pragma unroll
            for (int g = 0; g < 4; g++) {
                float s = gx_s[(b * 4 + g) * 4 + jj];
                #pragma unroll
                for (int k2 = 0; k2 < 16; k2++)
                    s += red_s[k2 * 580 + (g * 4 + jj) * 36 + b];
                gs[g] = s;
            }
            float ig = sigf(gs[0]);
            float fg = sigf(gs[1]);
            float gg = tanhf(gs[2]);
            float og = sigf(gs[3]);
            creg = fg * creg + ig * gg;
            hst[jj * 32 + b] = og * tanhf(creg);
            if (t == T_ - 1)
                dout[OUT_OFF_CN + L * (B_ * H_) + b * H_ + u0 + jj] = creg;
        }
        __syncthreads();

        // ---- publish h ----
        if (tid < 32) {
            float4 h4;
            h4.x = hst[tid]; h4.y = hst[32 + tid];
            h4.z = hst[64 + tid]; h4.w = hst[96 + tid];
            size_t didx = (size_t)tid * H_ + u0;
            *(float4*)(g_hbuf + cb * (B_ * H_) + didx) = h4;
            *(float4*)(oT + (size_t)t * (B_ * H_) + didx) = h4;
        }
        __syncthreads();

        // ---- barrier ----
        if (tid == 0) { __threadfence(); red_add(cnt, 1u); }
        if ((tid & 31) == 0) {
            unsigned tgt = 128u * (unsigned)(t + 2);
            while (ld_acq(cnt) < tgt) __nanosleep(32);
        }
        __syncthreads();
    }
}

// ---------------- FC: out = relu(h) @ fc_w^T + fc_b ----------------
#define FCP 8
__global__ __launch_bounds__(128, 8)
void fc_kernel(const float* __restrict__ fc_b, float* __restrict__ dout)
{
    __shared__ float hs[FCP * H_];
    __shared__ float red[4 * 32 * 33];

    const int tid  = threadIdx.x;
    const int blk  = blockIdx.x;
    const int w    = tid >> 5;
    const int lane = tid & 31;
    const bool hidden = (blk >= 8192);

    for (int q = tid; q < FCP * (H_ / 4); q += 128) {
        int p = q >> 7, c = q & 127;
        float4 v;
        if (!hidden) {
            int pair = blk * FCP + p;
            int b = pair >> 11, t = pair & 2047;
            v = *(const float4*)(g_out1T + ((size_t)t * B_ + b) * H_ + c * 4);
        } else {
            int p2 = (blk - 8192) * FCP + p;
            int l = p2 >> 5, b = p2 & 31;
            const float* sp = l ? g_out1T : g_out0T;
            v = *(const float4*)(sp + ((size_t)(T_ - 1) * B_ + b) * H_ + c * 4);
        }
        v.x = fmaxf(v.x, 0.f); v.y = fmaxf(v.y, 0.f);
        v.z = fmaxf(v.z, 0.f); v.w = fmaxf(v.w, 0.f);
        *(float4*)(hs + p * H_ + c * 4) = v;
    }
    __syncthreads();

    const int o4 = lane * 4;
    ull acc[FCP][2];
    #pragma unroll
    for (int p = 0; p < FCP; p++) { acc[p][0] = 0ull; acc[p][1] = 0ull; }

    #pragma unroll 4
    for (int i = 0; i < H_ / 4; ++i) {
        int k = w + i * 4;
        float4 wv = *(const float4*)(g_fcwT + k * OD_ + o4);
        ull wlo = pack2(wv.x, wv.y);
        ull whi = pack2(wv.z, wv.w);
        #pragma unroll
        for (int p = 0; p < FCP; p++) {
            float h = hs[p * H_ + k];
            ull hd = pack2(h, h);
            ffma2(acc[p][0], wlo, hd);
            ffma2(acc[p][1], whi, hd);
        }
    }

    {
        float* row = red + (w * 32 + lane) * 33;
        #pragma unroll
        for (int p = 0; p < FCP; p++) {
            row[p * 4 + 0] = __uint_as_float((unsigned)acc[p][0]);
            row[p * 4 + 1] = __uint_as_float((unsigned)(acc[p][0] >> 32));
            row[p * 4 + 2] = __uint_as_float((unsigned)acc[p][1]);
            row[p * 4 + 3] = __uint_as_float((unsigned)(acc[p][1] >> 32));
        }
    }
    __syncthreads();

    int p  = tid >> 4;
    int og = (tid & 15) * 8;
    size_t dst;
    if (!hidden) dst = (size_t)(blk * FCP + p) * OD_;
    else         dst = (size_t)OUT_OFF_HIDDEN + ((blk - 8192) * FCP + p) * OD_;
    #pragma unroll
    for (int oo = 0; oo < 8; oo++) {
        int o = og + oo;
        float s = fc_b[o];
        #pragma unroll
        for (int ww = 0; ww < 4; ww++)
            s += red[(ww * 32 + (o >> 2)) * 33 + p * 4 + (o & 3)];
        dout[dst + o] = s;
    }
}

// ---------------- host ----------------
#define LSTM_SMEM ((8192 + 16384 + 9280 + 512 + 128) * 4)   // 137,984 B

extern "C" void kernel_launch(void* const* d_in, const int* in_sizes, int n_in,
                              void* d_out, int out_size) {
    (void)in_sizes; (void)n_in; (void)out_size;
    const float* x     = (const float*)d_in[0];
    const float* w_ih0 = (const float*)d_in[1];
    const float* w_hh0 = (const float*)d_in[2];
    const float* b_ih0 = (const float*)d_in[3];
    const float* b_hh0 = (const float*)d_in[4];
    const float* w_ih1 = (const float*)d_in[5];
    const float* w_hh1 = (const float*)d_in[6];
    const float* b_ih1 = (const float*)d_in[7];
    const float* b_hh1 = (const float*)d_in[8];
    const float* fc_w  = (const float*)d_in[9];
    const float* fc_b  = (const float*)d_in[10];
    float* out = (float*)d_out;

    cudaFuncSetAttribute(lstm_rec_kernel<0>,
                         cudaFuncAttributeMaxDynamicSharedMemorySize, LSTM_SMEM);
    cudaFuncSetAttribute(lstm_rec_kernel<1>,
                         cudaFuncAttributeMaxDynamicSharedMemorySize, LSTM_SMEM);

    dim3 ggrid(512, 16);

    transpose_x_kernel<<<8192, NTHR>>>(x);                    // also resets barriers
    // layer 0
    transpose_w_kernel<IN0><<<(2048 * IN0) / NTHR, NTHR>>>(w_ih0);
    gemm_gx_kernel<IN0, 0><<<ggrid, 256>>>(b_ih0, b_hh0);
    lstm_rec_kernel<0><<<NBLK, NTHR, LSTM_SMEM>>>(w_hh0, out);
    // layer 1
    transpose_w_kernel<H_><<<(2048 * H_) / NTHR, NTHR>>>(w_ih1);
    gemm_gx_kernel<H_, 1><<<ggrid, 256>>>(b_ih1, b_hh1);
    lstm_rec_kernel<1><<<NBLK, NTHR, LSTM_SMEM>>>(w_hh1, out);
    // FC head
    transpose_fcw_kernel<<<256, NTHR>>>(fc_w);
    fc_kernel<<<8192 + 8, 128>>>(fc_b, out);
}